// round 6
// baseline (speedup 1.0000x reference)
#include <cuda_runtime.h>
#include <cuda_bf16.h>
#include <math.h>

// GLIF recurrence, T=4, single fused kernel.
// Grid = 4096: each block handles HALF the batches (8 of 16) of one channel.
// Per-channel params computed warp-parallel (lanes 0-7, one sigmoid each),
// amortized over 64 KiB of streaming traffic per block.
// 2-deep float4 double-buffering keeps regs ~40 -> 6 blocks/SM.
//
// x: (B=16, PLANE=2048, L=1024) fp32. out: final spike map, fp32 {0,1}.

#define GLIF_T     4
#define GLIF_PLANE 2048
#define GLIF_L     1024
#define GLIF_B     16
#define BATCH_PER_BLK 8

__global__ void __launch_bounds__(256) glif_kernel(
    const float* __restrict__ x,
    const float* __restrict__ alpha,
    const float* __restrict__ beta,
    const float* __restrict__ gamma,
    const float* __restrict__ tau,
    const float* __restrict__ Vth,
    const float* __restrict__ leak,
    const float* __restrict__ reVth,
    const float* __restrict__ conduct,
    float* __restrict__ out)
{
    __shared__ float sp[9];

    const int c    = blockIdx.x >> 1;          // channel
    const int half = blockIdx.x & 1;           // which 8 batches
    const int tid  = threadIdx.x;

    const size_t row4  = (size_t)GLIF_PLANE * (GLIF_L / 4);  // float4 per batch slice
    const size_t base4 = (size_t)(half * BATCH_PER_BLK) * row4
                       + (size_t)c * (GLIF_L / 4) + tid;
    const float4* xp = reinterpret_cast<const float4*>(x) + base4;
    float4*       op = reinterpret_cast<float4*>(out) + base4;

    // ---- prefetch first 2 batches (independent of params) ----
    float4 xv0 = __ldcs(xp);
    float4 xv1 = __ldcs(xp + row4);

    // ---- per-channel params: warp 0, lanes 0-7 each own one sigmoid ----
    if (tid < 32) {
        const int lane = tid;
        const float al = (__ldg(&alpha[c]) > 0.0f) ? 1.0f : 0.0f;  // arch_act(sigmoid)==(p>0)
        const float be = (__ldg(&beta[c])  > 0.0f) ? 1.0f : 0.0f;
        const float ga = (__ldg(&gamma[c]) > 0.0f) ? 1.0f : 0.0f;

        float v = 0.0f;
        if      (lane == 0) v = tau[c];
        else if (lane == 1) v = Vth[c];
        else if (lane == 2) v = leak[c];
        else if (lane == 3) v = reVth[c];
        else if (lane >= 4 && lane < 8) v = conduct[(lane - 4) * GLIF_PLANE + c];

        const float sig = 1.0f / (1.0f + expf(-v));

        if (lane == 0) {
            sp[0] = 1.0f - al * (1.0f - sig);   // A
            sp[1] = 1.0f - ga;                  // omg
        } else if (lane == 1) {
            sp[4] = sig;                        // vth
        } else if (lane == 2) {
            sp[2] = -((1.0f - al) * sig);       // negLk
        } else if (lane == 3) {
            sp[3] = -((1.0f - ga) * sig);       // negR
        } else if (lane >= 4 && lane < 8) {
            sp[5 + (lane - 4)] = 1.0f - be * (1.0f - sig);  // s_t
        }
    }
    __syncthreads();

    const float A     = sp[0];
    const float omg   = sp[1];
    const float negLk = sp[2];
    const float negR  = sp[3];
    const float vth   = sp[4];
    const float s0    = sp[5];
    const float sv[3] = {sp[6], sp[7], sp[8]};

    // ---- process 8 batches, double-buffered 2 at a time ----
#pragma unroll
    for (int i = 0; i < BATCH_PER_BLK; i += 2) {
        float4 nx0, nx1;
        if (i + 2 < BATCH_PER_BLK) {
            nx0 = __ldcs(xp + (size_t)(i + 2) * row4);
            nx1 = __ldcs(xp + (size_t)(i + 3) * row4);
        }

#pragma unroll
        for (int u = 0; u < 2; ++u) {
            const float4 xq = (u == 0) ? xv0 : xv1;
            float xl[4] = {xq.x, xq.y, xq.z, xq.w};
            float ov[4];
#pragma unroll
            for (int j = 0; j < 4; ++j) {
                const float xj = xl[j];
                // t=0: u=0, o=0 -> u1 = x*s0 - Lk
                float uu = fmaf(xj, s0, negLk);
                bool  o  = (uu > vth);
#pragma unroll
                for (int t = 0; t < 3; ++t) {
                    // reference order: ((A*u)*(1-ga*o) - Lk) + x*s - R*o
                    const float g = o ? omg : 1.0f;
                    float m = (A * uu) * g;
                    m = m + negLk;
                    m = fmaf(xj, sv[t], m);
                    if (o) m = m + negR;
                    o = (m > vth);
                    uu = m;
                }
                ov[j] = o ? 1.0f : 0.0f;
            }
            float4 res;
            res.x = ov[0]; res.y = ov[1]; res.z = ov[2]; res.w = ov[3];
            __stcs(op + (size_t)(i + u) * row4, res);
        }

        xv0 = nx0;
        xv1 = nx1;
    }
}

extern "C" void kernel_launch(void* const* d_in, const int* in_sizes, int n_in,
                              void* d_out, int out_size) {
    const float* x       = (const float*)d_in[0];
    const float* alpha   = (const float*)d_in[1];
    const float* beta    = (const float*)d_in[2];
    const float* gamma   = (const float*)d_in[3];
    const float* tau     = (const float*)d_in[4];
    const float* Vth     = (const float*)d_in[5];
    const float* leak    = (const float*)d_in[6];
    const float* reVth   = (const float*)d_in[7];
    const float* conduct = (const float*)d_in[8];
    float* out = (float*)d_out;

    const int n_blk = out_size / (GLIF_L * BATCH_PER_BLK);  // 4096
    glif_kernel<<<n_blk, 256>>>(x, alpha, beta, gamma, tau, Vth,
                                leak, reVth, conduct, out);
}

// round 7
// speedup vs baseline: 1.0059x; 1.0059x over previous
#include <cuda_runtime.h>
#include <cuda_bf16.h>
#include <math.h>
#include <stdint.h>

// GLIF recurrence, T=4. One block per channel (grid=2048, 256 threads),
// 16 batches/block, 4-deep double-buffered float4 streaming (R4 structure),
// recurrence arithmetic in packed f32x2 (Blackwell) — 2 elements/inst on the
// FMA pipe. Arithmetic ordering is bit-identical to the R4 scalar version.
//
// x: (B=16, PLANE=2048, L=1024) fp32. out: final spike map, fp32 {0,1}.

#define GLIF_T     4
#define GLIF_PLANE 2048
#define GLIF_L     1024
#define GLIF_B     16

// ---- packed f32x2 helpers ----
__device__ __forceinline__ uint64_t pk2(float lo, float hi) {
    uint64_t r;
    asm("mov.b64 %0, {%1, %2};" : "=l"(r) : "f"(lo), "f"(hi));
    return r;
}
__device__ __forceinline__ void upk2(uint64_t v, float& lo, float& hi) {
    asm("mov.b64 {%0, %1}, %2;" : "=f"(lo), "=f"(hi) : "l"(v));
}
__device__ __forceinline__ uint64_t fma2_(uint64_t a, uint64_t b, uint64_t c) {
    uint64_t d;
    asm("fma.rn.f32x2 %0, %1, %2, %3;" : "=l"(d) : "l"(a), "l"(b), "l"(c));
    return d;
}
__device__ __forceinline__ uint64_t mul2_(uint64_t a, uint64_t b) {
    uint64_t d;
    asm("mul.rn.f32x2 %0, %1, %2;" : "=l"(d) : "l"(a), "l"(b));
    return d;
}
__device__ __forceinline__ uint64_t add2_(uint64_t a, uint64_t b) {
    uint64_t d;
    asm("add.rn.f32x2 %0, %1, %2;" : "=l"(d) : "l"(a), "l"(b));
    return d;
}
__device__ __forceinline__ float setgt_(float a, float b) {
    float r;
    asm("set.gt.f32.f32 %0, %1, %2;" : "=f"(r) : "f"(a), "f"(b));
    return r;  // 1.0f if a > b else 0.0f
}

__global__ void __launch_bounds__(256) glif_kernel(
    const float* __restrict__ x,
    const float* __restrict__ alpha,
    const float* __restrict__ beta,
    const float* __restrict__ gamma,
    const float* __restrict__ tau,
    const float* __restrict__ Vth,
    const float* __restrict__ leak,
    const float* __restrict__ reVth,
    const float* __restrict__ conduct,
    float* __restrict__ out)
{
    __shared__ float sp[10];

    const int c   = blockIdx.x;            // channel
    const int tid = threadIdx.x;

    const size_t row4  = (size_t)GLIF_PLANE * (GLIF_L / 4);  // float4 per batch
    const size_t base4 = (size_t)c * (GLIF_L / 4) + tid;
    const float4* xp = reinterpret_cast<const float4*>(x) + base4;
    float4*       op = reinterpret_cast<float4*>(out) + base4;

    // ---- prefetch chunk 0 (independent of params) ----
    float4 xv[4];
#pragma unroll
    for (int u = 0; u < 4; ++u)
        xv[u] = __ldcs(xp + (size_t)u * row4);

    // ---- per-channel params: warp 0, lanes 0-7 each own one sigmoid ----
    if (tid < 32) {
        const int lane = tid;
        const float al = (__ldg(&alpha[c]) > 0.0f) ? 1.0f : 0.0f;  // arch_act(sigmoid)==(p>0)
        const float be = (__ldg(&beta[c])  > 0.0f) ? 1.0f : 0.0f;
        const float ga = (__ldg(&gamma[c]) > 0.0f) ? 1.0f : 0.0f;

        float v = 0.0f;
        if      (lane == 0) v = tau[c];
        else if (lane == 1) v = Vth[c];
        else if (lane == 2) v = leak[c];
        else if (lane == 3) v = reVth[c];
        else if (lane >= 4 && lane < 8) v = conduct[(lane - 4) * GLIF_PLANE + c];

        const float sig = 1.0f / (1.0f + expf(-v));

        if (lane == 0) {
            sp[0] = 1.0f - al * (1.0f - sig);   // A
            sp[1] = -ga;                        // negGa (g = 1 - ga*o)
        } else if (lane == 1) {
            sp[4] = sig;                        // vth
        } else if (lane == 2) {
            sp[2] = -((1.0f - al) * sig);       // negLk
        } else if (lane == 3) {
            sp[3] = -((1.0f - ga) * sig);       // negR
        } else if (lane >= 4 && lane < 8) {
            sp[5 + (lane - 4)] = 1.0f - be * (1.0f - sig);  // s_t
        }
    }
    __syncthreads();

    // packed per-channel constants
    const uint64_t A2     = pk2(sp[0], sp[0]);
    const uint64_t negGa2 = pk2(sp[1], sp[1]);
    const uint64_t negLk2 = pk2(sp[2], sp[2]);
    const uint64_t negR2  = pk2(sp[3], sp[3]);
    const float    vth    = sp[4];
    const uint64_t s02    = pk2(sp[5], sp[5]);
    uint64_t sT2[3];
    sT2[0] = pk2(sp[6], sp[6]);
    sT2[1] = pk2(sp[7], sp[7]);
    sT2[2] = pk2(sp[8], sp[8]);
    const uint64_t one2   = pk2(1.0f, 1.0f);

    // ---- stream 16 batches, double-buffered in chunks of 4 ----
#pragma unroll
    for (int chunk = 0; chunk < 4; ++chunk) {
        float4 nv[4];
        if (chunk < 3) {
#pragma unroll
            for (int u = 0; u < 4; ++u)
                nv[u] = __ldcs(xp + (size_t)((chunk + 1) * 4 + u) * row4);
        }

#pragma unroll
        for (int u = 0; u < 4; ++u) {
            const float4 xq = xv[u];
            float oo[4];   // final spikes for the 4 elements

#pragma unroll
            for (int p = 0; p < 2; ++p) {   // two packed pairs per float4
                const uint64_t x2 = (p == 0) ? pk2(xq.x, xq.y) : pk2(xq.z, xq.w);

                // t = 0: u=0, o=0  ->  u1 = x*s0 - Lk   (fused, as in R4)
                uint64_t m = fma2_(x2, s02, negLk2);
                float mlo, mhi;
                upk2(m, mlo, mhi);
                float olo = setgt_(mlo, vth);
                float ohi = setgt_(mhi, vth);

#pragma unroll
                for (int t = 0; t < 3; ++t) {
                    const uint64_t o2 = pk2(olo, ohi);
                    // reference order: ((A*u)*(1-ga*o) - Lk) + x*s - R*o
                    const uint64_t g = fma2_(negGa2, o2, one2);   // exact for o,ga in {0,1}
                    uint64_t a = mul2_(A2, m);
                    a = mul2_(a, g);
                    a = add2_(a, negLk2);
                    a = fma2_(x2, sT2[t], a);
                    m = fma2_(negR2, o2, a);    // exact: negR*o is exact for o in {0,1}
                    upk2(m, mlo, mhi);
                    olo = setgt_(mlo, vth);
                    ohi = setgt_(mhi, vth);
                }
                oo[2 * p]     = olo;
                oo[2 * p + 1] = ohi;
            }

            float4 res;
            res.x = oo[0]; res.y = oo[1]; res.z = oo[2]; res.w = oo[3];
            __stcs(op + (size_t)(chunk * 4 + u) * row4, res);
        }

#pragma unroll
        for (int u = 0; u < 4; ++u) xv[u] = nv[u];
    }
}

extern "C" void kernel_launch(void* const* d_in, const int* in_sizes, int n_in,
                              void* d_out, int out_size) {
    const float* x       = (const float*)d_in[0];
    const float* alpha   = (const float*)d_in[1];
    const float* beta    = (const float*)d_in[2];
    const float* gamma   = (const float*)d_in[3];
    const float* tau     = (const float*)d_in[4];
    const float* Vth     = (const float*)d_in[5];
    const float* leak    = (const float*)d_in[6];
    const float* reVth   = (const float*)d_in[7];
    const float* conduct = (const float*)d_in[8];
    float* out = (float*)d_out;

    glif_kernel<<<GLIF_PLANE, 256>>>(x, alpha, beta, gamma, tau, Vth,
                                     leak, reVth, conduct, out);
}